// round 1
// baseline (speedup 1.0000x reference)
#include <cuda_runtime.h>
#include <cstdint>

// LiveNet: y = relu(x @ W1 + b1) @ W2 + b2
// B=1048576, N_IN=64, N_MID=32, N_OUT=16, all fp32.
//
// Design (warp-cooperative, register-resident weights, f32x2 packed math):
//  - lane j of each warp owns mid-neuron j; its W1 column (64 f32) lives in
//    registers as 32 packed f32x2 (pairs over k).
//  - x rows staged to SMEM with cp.async (double buffered, 16 rows/tile/warp),
//    read back via broadcast LDS.128 -> 2x b64 -> fma.rn.f32x2.
//  - h (16x32 per tile) staged in SMEM (padded stride 36 floats to avoid the
//    2-way bank conflict between the two 16-lane halves in layer 2).
//  - layer 2: lane = (row_half = lane>>4, out = lane&15); W2 column (32 f32)
//    register-resident as 16 packed f32x2; h broadcast from SMEM.
//  - output stores are fully coalesced (128B per warp-instruction).

#define N_IN  64
#define N_MID 32
#define N_OUT 16
#define TILE  16
#define WARPS 4
#define HPAD  36   // h row stride in floats (144B, 16B-aligned, conflict-free)

typedef unsigned long long u64;

__device__ __forceinline__ u64 fma2(u64 a, u64 b, u64 c) {
    u64 d;
    asm("fma.rn.f32x2 %0, %1, %2, %3;" : "=l"(d) : "l"(a), "l"(b), "l"(c));
    return d;
}
__device__ __forceinline__ u64 pack2(float lo, float hi) {
    u64 d;
    asm("mov.b64 %0, {%1, %2};" : "=l"(d) : "f"(lo), "f"(hi));
    return d;
}
__device__ __forceinline__ void unpack2(u64 v, float& lo, float& hi) {
    asm("mov.b64 {%0, %1}, %2;" : "=f"(lo), "=f"(hi) : "l"(v));
}
__device__ __forceinline__ void lds_v2u64(uint32_t addr, u64& a, u64& b) {
    asm volatile("ld.shared.v2.b64 {%0, %1}, [%2];" : "=l"(a), "=l"(b) : "r"(addr));
}
__device__ __forceinline__ void sts_f32(uint32_t addr, float v) {
    asm volatile("st.shared.f32 [%0], %1;" :: "r"(addr), "f"(v));
}
__device__ __forceinline__ void cp16(uint32_t smem, const void* gmem) {
    asm volatile("cp.async.cg.shared.global [%0], [%1], 16;" :: "r"(smem), "l"(gmem));
}
__device__ __forceinline__ void cp_commit() {
    asm volatile("cp.async.commit_group;" ::: "memory");
}
template <int N>
__device__ __forceinline__ void cp_wait() {
    asm volatile("cp.async.wait_group %0;" :: "n"(N) : "memory");
}

__global__ __launch_bounds__(WARPS * 32, 3)
void livenet_kernel(const float* __restrict__ x,
                    const float* __restrict__ W1,
                    const float* __restrict__ b1,
                    const float* __restrict__ W2,
                    const float* __restrict__ b2,
                    float* __restrict__ y,
                    int nTiles) {
    __shared__ float xs[WARPS][2][TILE * N_IN];   // 4 * 2 * 1024 f = 32 KB
    __shared__ float hs[WARPS][TILE * HPAD];      // 4 * 576 f    = 9 KB

    const int wid  = threadIdx.x >> 5;
    const int lane = threadIdx.x & 31;

    // ---- register-resident weights ----
    u64 w1p[N_IN / 2];                 // lane j owns W1[:, j], packed over k
    #pragma unroll
    for (int m = 0; m < N_IN / 2; m++)
        w1p[m] = pack2(W1[(2 * m) * N_MID + lane], W1[(2 * m + 1) * N_MID + lane]);
    const float b1j = b1[lane];

    const int out = lane & (N_OUT - 1); // 0..15
    const int rs  = lane >> 4;          // 0 or 1: which row of the pair
    u64 w2p[N_MID / 2];                 // lane owns W2[:, out], packed over k
    #pragma unroll
    for (int m = 0; m < N_MID / 2; m++)
        w2p[m] = pack2(W2[(2 * m) * N_OUT + out], W2[(2 * m + 1) * N_OUT + out]);
    const float b2o = b2[out];

    const uint32_t xs0 = (uint32_t)__cvta_generic_to_shared(&xs[wid][0][0]);
    const uint32_t xs1 = (uint32_t)__cvta_generic_to_shared(&xs[wid][1][0]);
    const uint32_t hsb = (uint32_t)__cvta_generic_to_shared(&hs[wid][0]);

    const int gw     = blockIdx.x * WARPS + wid;
    const int stride = gridDim.x * WARPS;

    // prologue: stage first tile
    if (gw < nTiles) {
        const float4* src = (const float4*)(x + (size_t)gw * TILE * N_IN);
        #pragma unroll
        for (int i = 0; i < 8; i++)
            cp16(xs0 + (uint32_t)(i * 32 + lane) * 16, src + i * 32 + lane);
        cp_commit();
    }

    int buf = 0;
    for (int t = gw; t < nTiles; t += stride) {
        const int nt = t + stride;
        const bool hasNext = nt < nTiles;
        if (hasNext) {
            const uint32_t sb_next = buf ? xs0 : xs1;
            const float4* src = (const float4*)(x + (size_t)nt * TILE * N_IN);
            #pragma unroll
            for (int i = 0; i < 8; i++)
                cp16(sb_next + (uint32_t)(i * 32 + lane) * 16, src + i * 32 + lane);
            cp_commit();
            cp_wait<1>();   // current tile's group is complete
        } else {
            cp_wait<0>();
        }
        __syncwarp();

        const uint32_t sb = buf ? xs1 : xs0;

        // ---- layer 1: h[r][lane] = relu(dot(x[r], W1[:,lane]) + b1) ----
        #pragma unroll
        for (int r = 0; r < TILE; r++) {
            u64 a0 = 0ull, a1 = 0ull;
            #pragma unroll
            for (int q = 0; q < 16; q++) {       // 16 x LDS.128 per row
                u64 p0, p1;
                lds_v2u64(sb + (uint32_t)(r * 256 + q * 16), p0, p1);
                a0 = fma2(p0, w1p[2 * q],     a0);
                a1 = fma2(p1, w1p[2 * q + 1], a1);
            }
            float l0, h0, l1, h1;
            unpack2(a0, l0, h0);
            unpack2(a1, l1, h1);
            float h = (l0 + h0) + (l1 + h1) + b1j;
            h = fmaxf(h, 0.0f);
            sts_f32(hsb + (uint32_t)(r * HPAD + lane) * 4, h);
        }
        __syncwarp();

        // ---- layer 2: y[r][out] = dot(h[r], W2[:,out]) + b2 ----
        float* ybase = y + (size_t)t * TILE * N_OUT;
        #pragma unroll
        for (int rp = 0; rp < TILE / 2; rp++) {
            const int r = rp * 2 + rs;
            u64 a0 = 0ull, a1 = 0ull;
            #pragma unroll
            for (int q = 0; q < 8; q++) {        // 8 x LDS.128 per h row
                u64 p0, p1;
                lds_v2u64(hsb + (uint32_t)(r * HPAD * 4 + q * 16), p0, p1);
                a0 = fma2(p0, w2p[2 * q],     a0);
                a1 = fma2(p1, w2p[2 * q + 1], a1);
            }
            float l0, h0, l1, h1;
            unpack2(a0, l0, h0);
            unpack2(a1, l1, h1);
            // addresses: (rp*2+rs)*16 + out = rp*32 + lane  -> fully coalesced
            ybase[rp * 32 + lane] = (l0 + h0) + (l1 + h1) + b2o;
        }
        __syncwarp();
        buf ^= 1;
    }
}

extern "C" void kernel_launch(void* const* d_in, const int* in_sizes, int n_in,
                              void* d_out, int out_size) {
    const float* x  = (const float*)d_in[0];
    const float* W1 = (const float*)d_in[1];
    const float* b1 = (const float*)d_in[2];
    const float* W2 = (const float*)d_in[3];
    const float* b2 = (const float*)d_in[4];
    float* y = (float*)d_out;

    const int B = in_sizes[0] / N_IN;         // 1048576
    const int nTiles = B / TILE;              // 65536 (B divisible by 16)

    const int blocks = 456;                   // 152 SMs * 3 blocks/SM
    livenet_kernel<<<blocks, WARPS * 32>>>(x, W1, b1, W2, b2, y, nTiles);
}

// round 2
// speedup vs baseline: 1.1157x; 1.1157x over previous
#include <cuda_runtime.h>
#include <cstdint>

// LiveNet: y = relu(x @ W1 + b1) @ W2 + b2
// B=1048576, N_IN=64, N_MID=32, N_OUT=16, all fp32.
//
// R2: half-warp K-split for layer 1 to halve LDS wavefronts (the R1 ncu
// profile showed L1tex = 92.9% binding, fma only 47.6%).
//  - lanes 0-15 own k in [0,32), lanes 16-31 own k in [32,64)
//  - lane (hl, j2): computes neurons {2*j2, 2*j2+1} partials over its k-half
//  - x tile stored per-row as [128B half0][16B pad][128B half1] (stride 272B)
//    so the two half-warp broadcast addresses hit disjoint bank groups
//    (A1 = A0 + 144 => +16 mod 128): each LDS.128 = 1 wavefront.
//  - cross-half reduce: one packed f32x2 shfl.bfly(16) + add per row.
//  - layer 2 unchanged (HPAD=36 keeps the two row-addresses bank-disjoint).

#define N_IN  64
#define N_MID 32
#define N_OUT 16
#define TILE  16
#define WARPS 4
#define HPAD  36      // h row stride in floats (144B => +16 mod 128)
#define XSTRIDE 272   // x row stride in bytes: 128 + 16 pad + 128

typedef unsigned long long u64;

__device__ __forceinline__ u64 fma2(u64 a, u64 b, u64 c) {
    u64 d;
    asm("fma.rn.f32x2 %0, %1, %2, %3;" : "=l"(d) : "l"(a), "l"(b), "l"(c));
    return d;
}
__device__ __forceinline__ u64 add2(u64 a, u64 b) {
    u64 d;
    asm("add.rn.f32x2 %0, %1, %2;" : "=l"(d) : "l"(a), "l"(b));
    return d;
}
__device__ __forceinline__ u64 pack2(float lo, float hi) {
    u64 d;
    asm("mov.b64 %0, {%1, %2};" : "=l"(d) : "f"(lo), "f"(hi));
    return d;
}
__device__ __forceinline__ void unpack2(u64 v, float& lo, float& hi) {
    asm("mov.b64 {%0, %1}, %2;" : "=f"(lo), "=f"(hi) : "l"(v));
}
__device__ __forceinline__ void lds_v2u64(uint32_t addr, u64& a, u64& b) {
    asm volatile("ld.shared.v2.b64 {%0, %1}, [%2];" : "=l"(a), "=l"(b) : "r"(addr));
}
__device__ __forceinline__ void sts_v2f32(uint32_t addr, float a, float b) {
    asm volatile("st.shared.v2.f32 [%0], {%1, %2};" :: "r"(addr), "f"(a), "f"(b));
}
__device__ __forceinline__ void cp16(uint32_t smem, const void* gmem) {
    asm volatile("cp.async.cg.shared.global [%0], [%1], 16;" :: "r"(smem), "l"(gmem));
}
__device__ __forceinline__ void cp_commit() {
    asm volatile("cp.async.commit_group;" ::: "memory");
}
template <int N>
__device__ __forceinline__ void cp_wait() {
    asm volatile("cp.async.wait_group %0;" :: "n"(N) : "memory");
}

__global__ __launch_bounds__(WARPS * 32, 3)
void livenet_kernel(const float* __restrict__ x,
                    const float* __restrict__ W1,
                    const float* __restrict__ b1,
                    const float* __restrict__ W2,
                    const float* __restrict__ b2,
                    float* __restrict__ y,
                    int nTiles) {
    __shared__ char  xs[WARPS][2][TILE * XSTRIDE];  // 4*2*4352B = 34 KB
    __shared__ float hs[WARPS][TILE * HPAD];        // 9 KB

    const int wid  = threadIdx.x >> 5;
    const int lane = threadIdx.x & 31;
    const int hl   = lane >> 4;            // k-half: 0 or 1
    const int j2   = lane & 15;            // neuron pair index
    const int k0   = hl * 32;              // this lane's k base

    // ---- layer-1 weights: neurons {2*j2, 2*j2+1}, k in [k0, k0+32) ----
    u64 w1A[16], w1B[16];
    const int nA = 2 * j2, nB = 2 * j2 + 1;
    #pragma unroll
    for (int q = 0; q < 16; q++) {
        w1A[q] = pack2(W1[(k0 + 2 * q) * N_MID + nA], W1[(k0 + 2 * q + 1) * N_MID + nA]);
        w1B[q] = pack2(W1[(k0 + 2 * q) * N_MID + nB], W1[(k0 + 2 * q + 1) * N_MID + nB]);
    }
    const u64 b1p = pack2(b1[nA], b1[nB]);

    // ---- layer-2 weights: lane = (row-slot rs, out) ----
    const int out = lane & (N_OUT - 1);
    const int rs  = lane >> 4;
    u64 w2p[N_MID / 2];
    #pragma unroll
    for (int m = 0; m < N_MID / 2; m++)
        w2p[m] = pack2(W2[(2 * m) * N_OUT + out], W2[(2 * m + 1) * N_OUT + out]);
    const float b2o = b2[out];

    const uint32_t xs0 = (uint32_t)__cvta_generic_to_shared(&xs[wid][0][0]);
    const uint32_t xs1 = (uint32_t)__cvta_generic_to_shared(&xs[wid][1][0]);
    const uint32_t hsb = (uint32_t)__cvta_generic_to_shared(&hs[wid][0]);

    // precompute cp.async dest offsets (loop-invariant per lane)
    uint32_t dstoff[8];
    uint32_t srcidx[8];
    #pragma unroll
    for (int i = 0; i < 8; i++) {
        const int c   = i * 32 + lane;      // 16B chunk id, 0..255
        const int row = c >> 4;
        const int kc  = c & 15;
        dstoff[i] = (uint32_t)(row * XSTRIDE + kc * 16 + ((kc & 8) << 1)); // +16 skew for half1
        srcidx[i] = (uint32_t)c;
    }

    const int gw     = blockIdx.x * WARPS + wid;
    const int stride = gridDim.x * WARPS;

    if (gw < nTiles) {
        const float4* src = (const float4*)(x + (size_t)gw * TILE * N_IN);
        #pragma unroll
        for (int i = 0; i < 8; i++)
            cp16(xs0 + dstoff[i], src + srcidx[i]);
        cp_commit();
    }

    int buf = 0;
    for (int t = gw; t < nTiles; t += stride) {
        const int nt = t + stride;
        if (nt < nTiles) {
            const uint32_t sb_next = buf ? xs0 : xs1;
            const float4* src = (const float4*)(x + (size_t)nt * TILE * N_IN);
            #pragma unroll
            for (int i = 0; i < 8; i++)
                cp16(sb_next + dstoff[i], src + srcidx[i]);
            cp_commit();
            cp_wait<1>();
        } else {
            cp_wait<0>();
        }
        __syncwarp();

        const uint32_t sb = (buf ? xs1 : xs0) + (uint32_t)(hl * 144); // half-select

        // ---- layer 1: half-warp K-split ----
        #pragma unroll
        for (int r = 0; r < TILE; r++) {
            u64 aA0 = 0ull, aA1 = 0ull, aB0 = 0ull, aB1 = 0ull;
            const uint32_t rb = sb + (uint32_t)(r * XSTRIDE);
            #pragma unroll
            for (int q = 0; q < 8; q++) {        // 8 x LDS.128 per row (1 wf each)
                u64 p0, p1;
                lds_v2u64(rb + (uint32_t)(q * 16), p0, p1);
                aA0 = fma2(p0, w1A[2 * q],     aA0);
                aA1 = fma2(p1, w1A[2 * q + 1], aA1);
                aB0 = fma2(p0, w1B[2 * q],     aB0);
                aB1 = fma2(p1, w1B[2 * q + 1], aB1);
            }
            const u64 aA = add2(aA0, aA1);
            const u64 aB = add2(aB0, aB1);
            float la, ha, lb, hb;
            unpack2(aA, la, ha);
            unpack2(aB, lb, hb);
            u64 v = pack2(la + ha, lb + hb);     // (partial_nA, partial_nB)
            v = add2(v, __shfl_xor_sync(0xffffffffu, v, 16));  // cross-half reduce
            v = add2(v, b1p);
            float fA, fB;
            unpack2(v, fA, fB);
            fA = fmaxf(fA, 0.0f);
            fB = fmaxf(fB, 0.0f);
            if (hl == 0)
                sts_v2f32(hsb + (uint32_t)(r * HPAD + nA) * 4, fA, fB);
        }
        __syncwarp();

        // ---- layer 2: y[r][out] = dot(h[r], W2[:,out]) + b2 ----
        float* ybase = y + (size_t)t * TILE * N_OUT;
        #pragma unroll
        for (int rp = 0; rp < TILE / 2; rp++) {
            const int r = rp * 2 + rs;
            u64 a0 = 0ull, a1 = 0ull;
            const uint32_t rb = hsb + (uint32_t)(r * HPAD * 4);
            #pragma unroll
            for (int q = 0; q < 8; q++) {
                u64 p0, p1;
                lds_v2u64(rb + (uint32_t)(q * 16), p0, p1);
                a0 = fma2(p0, w2p[2 * q],     a0);
                a1 = fma2(p1, w2p[2 * q + 1], a1);
            }
            const u64 a = add2(a0, a1);
            float lo, hi;
            unpack2(a, lo, hi);
            ybase[rp * 32 + lane] = lo + hi + b2o;   // coalesced
        }
        __syncwarp();
        buf ^= 1;
    }
}

extern "C" void kernel_launch(void* const* d_in, const int* in_sizes, int n_in,
                              void* d_out, int out_size) {
    const float* x  = (const float*)d_in[0];
    const float* W1 = (const float*)d_in[1];
    const float* b1 = (const float*)d_in[2];
    const float* W2 = (const float*)d_in[3];
    const float* b2 = (const float*)d_in[4];
    float* y = (float*)d_out;

    const int B = in_sizes[0] / N_IN;
    const int nTiles = B / TILE;

    const int blocks = 456;                  // 152 SMs * 3 blocks
    livenet_kernel<<<blocks, WARPS * 32>>>(x, W1, b1, W2, b2, y, nTiles);
}

// round 3
// speedup vs baseline: 1.1279x; 1.0109x over previous
#include <cuda_runtime.h>
#include <cstdint>

// LiveNet: y = relu(x @ W1 + b1) @ W2 + b2
// B=1048576, N_IN=64, N_MID=32, N_OUT=16, all fp32.
//
// R3: occupancy push. R2 showed no pipe saturated (fma 54%, L1 66%, DRAM 28%)
// with issue at 41.6% and only 12 warps/SM (regs=164 -> 3 blocks). This round:
//  - __launch_bounds__(128, 4): regs <= 128 -> 16 warps/SM (RF ceiling).
//  - grid = 608 (152 SMs x 4 blocks), max smem carveout for co-residency.
//  - L1: 2 packed accumulator chains per row (was 4 + combines), unroll 4.
//  - L2: 1 chain per row-pair iteration (saves add2s + regs).
// Same half-warp K-split layout as R2 (LDS wavefront-optimal).

#define N_IN  64
#define N_MID 32
#define N_OUT 16
#define TILE  16
#define WARPS 4
#define HPAD  36      // h row stride in floats (144B => +16 mod 128)
#define XSTRIDE 272   // x row stride in bytes: 128 + 16 pad + 128

typedef unsigned long long u64;

__device__ __forceinline__ u64 fma2(u64 a, u64 b, u64 c) {
    u64 d;
    asm("fma.rn.f32x2 %0, %1, %2, %3;" : "=l"(d) : "l"(a), "l"(b), "l"(c));
    return d;
}
__device__ __forceinline__ u64 add2(u64 a, u64 b) {
    u64 d;
    asm("add.rn.f32x2 %0, %1, %2;" : "=l"(d) : "l"(a), "l"(b));
    return d;
}
__device__ __forceinline__ u64 pack2(float lo, float hi) {
    u64 d;
    asm("mov.b64 %0, {%1, %2};" : "=l"(d) : "f"(lo), "f"(hi));
    return d;
}
__device__ __forceinline__ void unpack2(u64 v, float& lo, float& hi) {
    asm("mov.b64 {%0, %1}, %2;" : "=f"(lo), "=f"(hi) : "l"(v));
}
__device__ __forceinline__ void lds_v2u64(uint32_t addr, u64& a, u64& b) {
    asm volatile("ld.shared.v2.b64 {%0, %1}, [%2];" : "=l"(a), "=l"(b) : "r"(addr));
}
__device__ __forceinline__ void sts_v2f32(uint32_t addr, float a, float b) {
    asm volatile("st.shared.v2.f32 [%0], {%1, %2};" :: "r"(addr), "f"(a), "f"(b));
}
__device__ __forceinline__ void cp16(uint32_t smem, const void* gmem) {
    asm volatile("cp.async.cg.shared.global [%0], [%1], 16;" :: "r"(smem), "l"(gmem));
}
__device__ __forceinline__ void cp_commit() {
    asm volatile("cp.async.commit_group;" ::: "memory");
}
template <int N>
__device__ __forceinline__ void cp_wait() {
    asm volatile("cp.async.wait_group %0;" :: "n"(N) : "memory");
}

__global__ __launch_bounds__(WARPS * 32, 4)
void livenet_kernel(const float* __restrict__ x,
                    const float* __restrict__ W1,
                    const float* __restrict__ b1,
                    const float* __restrict__ W2,
                    const float* __restrict__ b2,
                    float* __restrict__ y,
                    int nTiles) {
    __shared__ char  xs[WARPS][2][TILE * XSTRIDE];  // 34 KB
    __shared__ float hs[WARPS][TILE * HPAD];        // 9 KB

    const int wid  = threadIdx.x >> 5;
    const int lane = threadIdx.x & 31;
    const int hl   = lane >> 4;            // k-half: 0 or 1
    const int j2   = lane & 15;            // neuron pair index
    const int k0   = hl * 32;              // this lane's k base

    // ---- layer-1 weights: neurons {2*j2, 2*j2+1}, k in [k0, k0+32) ----
    u64 w1A[16], w1B[16];
    const int nA = 2 * j2, nB = 2 * j2 + 1;
    #pragma unroll
    for (int q = 0; q < 16; q++) {
        w1A[q] = pack2(W1[(k0 + 2 * q) * N_MID + nA], W1[(k0 + 2 * q + 1) * N_MID + nA]);
        w1B[q] = pack2(W1[(k0 + 2 * q) * N_MID + nB], W1[(k0 + 2 * q + 1) * N_MID + nB]);
    }
    const u64 b1p = pack2(b1[nA], b1[nB]);

    // ---- layer-2 weights: lane = (row-slot rs, out) ----
    const int out = lane & (N_OUT - 1);
    const int rs  = lane >> 4;
    u64 w2p[N_MID / 2];
    #pragma unroll
    for (int m = 0; m < N_MID / 2; m++)
        w2p[m] = pack2(W2[(2 * m) * N_OUT + out], W2[(2 * m + 1) * N_OUT + out]);
    const float b2o = b2[out];

    const uint32_t xs0 = (uint32_t)__cvta_generic_to_shared(&xs[wid][0][0]);
    const uint32_t xs1 = (uint32_t)__cvta_generic_to_shared(&xs[wid][1][0]);
    const uint32_t hsb = (uint32_t)__cvta_generic_to_shared(&hs[wid][0]);

    // cp.async destination offset for chunk c = i*32+lane (16B chunks):
    //   row = c>>4, kc = c&15, dst = row*XSTRIDE + kc*16 + 16*(kc>=8)
    const int c0   = lane;
    const int row0 = c0 >> 4, kc0 = c0 & 15;
    const uint32_t doff0 = (uint32_t)(row0 * XSTRIDE + kc0 * 16 + ((kc0 & 8) << 1));
    // chunks advance by 32 per i: row += 2, pattern repeats (32 = 2 full rows)
    const uint32_t dstep = 2 * XSTRIDE;

    const int gw     = blockIdx.x * WARPS + wid;
    const int stride = gridDim.x * WARPS;

    if (gw < nTiles) {
        const float4* src = (const float4*)(x + (size_t)gw * TILE * N_IN) + lane;
        #pragma unroll
        for (int i = 0; i < 8; i++)
            cp16(xs0 + doff0 + i * dstep, src + i * 32);
        cp_commit();
    }

    int buf = 0;
    for (int t = gw; t < nTiles; t += stride) {
        const int nt = t + stride;
        if (nt < nTiles) {
            const uint32_t sb_next = buf ? xs0 : xs1;
            const float4* src = (const float4*)(x + (size_t)nt * TILE * N_IN) + lane;
            #pragma unroll
            for (int i = 0; i < 8; i++)
                cp16(sb_next + doff0 + i * dstep, src + i * 32);
            cp_commit();
            cp_wait<1>();
        } else {
            cp_wait<0>();
        }
        __syncwarp();

        const uint32_t sb = (buf ? xs1 : xs0) + (uint32_t)(hl * 144); // half-select

        // ---- layer 1: half-warp K-split, 2 packed chains per row ----
        #pragma unroll 4
        for (int r = 0; r < TILE; r++) {
            u64 aA = 0ull, aB = 0ull;
            const uint32_t rb = sb + (uint32_t)(r * XSTRIDE);
            #pragma unroll
            for (int q = 0; q < 8; q++) {        // 8 x LDS.128 per row (1 wf each)
                u64 p0, p1;
                lds_v2u64(rb + (uint32_t)(q * 16), p0, p1);
                aA = fma2(p0, w1A[2 * q],     aA);
                aA = fma2(p1, w1A[2 * q + 1], aA);
                aB = fma2(p0, w1B[2 * q],     aB);
                aB = fma2(p1, w1B[2 * q + 1], aB);
            }
            float la, ha, lb, hb;
            unpack2(aA, la, ha);
            unpack2(aB, lb, hb);
            u64 v = pack2(la + ha, lb + hb);     // (partial_nA, partial_nB)
            v = add2(v, __shfl_xor_sync(0xffffffffu, v, 16));  // cross-half reduce
            v = add2(v, b1p);
            float fA, fB;
            unpack2(v, fA, fB);
            fA = fmaxf(fA, 0.0f);
            fB = fmaxf(fB, 0.0f);
            if (hl == 0)
                sts_v2f32(hsb + (uint32_t)(r * HPAD + nA) * 4, fA, fB);
        }
        __syncwarp();

        // ---- layer 2: y[r][out] = dot(h[r], W2[:,out]) + b2 ----
        float* ybase = y + (size_t)t * TILE * N_OUT;
        #pragma unroll
        for (int rp = 0; rp < TILE / 2; rp++) {
            const int r = rp * 2 + rs;
            u64 a = 0ull;
            const uint32_t rb = hsb + (uint32_t)(r * HPAD * 4);
            #pragma unroll
            for (int q = 0; q < 8; q++) {
                u64 p0, p1;
                lds_v2u64(rb + (uint32_t)(q * 16), p0, p1);
                a = fma2(p0, w2p[2 * q],     a);
                a = fma2(p1, w2p[2 * q + 1], a);
            }
            float lo, hi;
            unpack2(a, lo, hi);
            ybase[rp * 32 + lane] = lo + hi + b2o;   // coalesced
        }
        __syncwarp();
        buf ^= 1;
    }
}

extern "C" void kernel_launch(void* const* d_in, const int* in_sizes, int n_in,
                              void* d_out, int out_size) {
    const float* x  = (const float*)d_in[0];
    const float* W1 = (const float*)d_in[1];
    const float* b1 = (const float*)d_in[2];
    const float* W2 = (const float*)d_in[3];
    const float* b2 = (const float*)d_in[4];
    float* y = (float*)d_out;

    const int B = in_sizes[0] / N_IN;
    const int nTiles = B / TILE;

    // Allow 4 blocks x 43.5 KB static smem to co-reside per SM.
    static int carveout_set = 0;
    if (!carveout_set) {
        cudaFuncSetAttribute(livenet_kernel,
                             cudaFuncAttributePreferredSharedMemoryCarveout, 100);
        carveout_set = 1;
    }

    const int blocks = 608;                  // 152 SMs x 4 blocks
    livenet_kernel<<<blocks, WARPS * 32>>>(x, W1, b1, W2, b2, y, nTiles);
}

// round 5
// speedup vs baseline: 1.8192x; 1.6130x over previous
#include <cuda_runtime.h>
#include <cuda_bf16.h>
#include <cstdint>

// LiveNet: y = relu(x @ W1 + b1) @ W2 + b2
// B=1048576, N_IN=64, N_MID=32, N_OUT=16, fp32.
//
// R5: tcgen05 is 'a'-gated and the harness targets plain sm_103, so use
// warp-level mma.sync (HMMA) instead — bf16x3 split precision
// (AhBh + AhBl + AlBh, fp32 accumulate) for both GEMMs.
//  - A fragments built straight from coalesced LDG.64 (no smem for x).
//  - GEMM1 D fragment == GEMM2 A fragment layout: relu+cvt in registers.
//  - W1/W2/b1/b2 pre-built as per-lane fragments in 12KB smem (LDS.64/use).
//  - bias folded in as the C operand of the first mma of each chain.
//  - main loop has zero synchronization; warps independent; 16 rows/warp/iter.

typedef uint32_t u32;

__device__ __forceinline__ u32 cvt_bf16x2(float hi, float lo) {
    u32 r; asm("cvt.rn.bf16x2.f32 %0, %1, %2;" : "=r"(r) : "f"(hi), "f"(lo)); return r;
}
// split pair (x0=k even -> low bf16, x1=k odd -> high bf16)
__device__ __forceinline__ void split2(float x0, float x1, u32& hi, u32& lo) {
    hi = cvt_bf16x2(x1, x0);
    const float e0 = __uint_as_float(__byte_perm(hi, 0, 0x1044));
    const float e1 = __uint_as_float(__byte_perm(hi, 0, 0x3244));
    lo = cvt_bf16x2(x1 - e1, x0 - e0);
}
__device__ __forceinline__ void mma_bf16(float& d0, float& d1, float& d2, float& d3,
                                         u32 a0, u32 a1, u32 a2, u32 a3,
                                         u32 b0, u32 b1) {
    asm("mma.sync.aligned.m16n8k16.row.col.f32.bf16.bf16.f32 "
        "{%0,%1,%2,%3}, {%4,%5,%6,%7}, {%8,%9}, {%0,%1,%2,%3};"
        : "+f"(d0), "+f"(d1), "+f"(d2), "+f"(d3)
        : "r"(a0), "r"(a1), "r"(a2), "r"(a3), "r"(b0), "r"(b1));
}

__global__ __launch_bounds__(64)
void livenet_mma(const float* __restrict__ x,
                 const float* __restrict__ W1,
                 const float* __restrict__ b1,
                 const float* __restrict__ W2,
                 const float* __restrict__ b2,
                 float* __restrict__ y,
                 int nTiles) {
    // per-lane weight fragments, shared by both warps of the CTA
    __shared__ uint2  sB1h[4][4][32];   // [ntile][kstep][lane] GEMM1 W hi
    __shared__ uint2  sB1l[4][4][32];   //                       GEMM1 W lo
    __shared__ uint2  sB2h[2][2][32];   // [ntile][kstep][lane] GEMM2 W hi
    __shared__ uint2  sB2l[2][2][32];
    __shared__ float2 sb1[4][32];       // bias fragments (C operand pairs)
    __shared__ float2 sb2[2][32];

    const int tid  = threadIdx.x;
    const int wid  = tid >> 5;
    const int lane = tid & 31;
    const int g = lane >> 2;     // fragment group row
    const int t = lane & 3;      // thread-in-group

    // ---- one-time fragment build (warp 0) ----
    if (wid == 0) {
        #pragma unroll
        for (int n = 0; n < 4; n++) {
            #pragma unroll
            for (int s = 0; s < 4; s++) {
                const int col = 8 * n + g;
                const float w00 = W1[(16 * s + 2 * t)     * 32 + col];
                const float w01 = W1[(16 * s + 2 * t + 1) * 32 + col];
                const float w10 = W1[(16 * s + 2 * t + 8) * 32 + col];
                const float w11 = W1[(16 * s + 2 * t + 9) * 32 + col];
                u32 h0, l0, h1, l1;
                split2(w00, w01, h0, l0);
                split2(w10, w11, h1, l1);
                sB1h[n][s][lane] = make_uint2(h0, h1);
                sB1l[n][s][lane] = make_uint2(l0, l1);
            }
            sb1[n][lane] = make_float2(b1[8 * n + 2 * t], b1[8 * n + 2 * t + 1]);
        }
        #pragma unroll
        for (int n = 0; n < 2; n++) {
            #pragma unroll
            for (int k = 0; k < 2; k++) {
                const int col = 8 * n + g;
                const float w00 = W2[(16 * k + 2 * t)     * 16 + col];
                const float w01 = W2[(16 * k + 2 * t + 1) * 16 + col];
                const float w10 = W2[(16 * k + 2 * t + 8) * 16 + col];
                const float w11 = W2[(16 * k + 2 * t + 9) * 16 + col];
                u32 h0, l0, h1, l1;
                split2(w00, w01, h0, l0);
                split2(w10, w11, h1, l1);
                sB2h[n][k][lane] = make_uint2(h0, h1);
                sB2l[n][k][lane] = make_uint2(l0, l1);
            }
            sb2[n][lane] = make_float2(b2[8 * n + 2 * t], b2[8 * n + 2 * t + 1]);
        }
    }
    __syncthreads();

    const int gw     = blockIdx.x * 2 + wid;
    const int stride = gridDim.x * 2;

    for (int tile = gw; tile < nTiles; tile += stride) {
        const float* xb = x + (size_t)tile * (16 * 64);

        // ---- load x: lane (g,t) takes rows g / g+8, k = 2t + 8u ----
        float2 xv[2][8];
        #pragma unroll
        for (int rh = 0; rh < 2; rh++)
            #pragma unroll
            for (int u = 0; u < 8; u++)
                xv[rh][u] = *(const float2*)(xb + (size_t)(g + 8 * rh) * 64 + 2 * t + 8 * u);

        // ---- A fragments per k-step (hi/lo split) ----
        u32 hiA[4][4], loA[4][4];
        #pragma unroll
        for (int s = 0; s < 4; s++) {
            split2(xv[0][2 * s].x,     xv[0][2 * s].y,     hiA[s][0], loA[s][0]); // a0
            split2(xv[1][2 * s].x,     xv[1][2 * s].y,     hiA[s][1], loA[s][1]); // a1
            split2(xv[0][2 * s + 1].x, xv[0][2 * s + 1].y, hiA[s][2], loA[s][2]); // a2
            split2(xv[1][2 * s + 1].x, xv[1][2 * s + 1].y, hiA[s][3], loA[s][3]); // a3
        }

        // ---- GEMM1: D1[n] = x @ W1[:,8n:8n+8] + b1, 3-term split ----
        float D1[4][4];
        #pragma unroll
        for (int n = 0; n < 4; n++) {
            const float2 c = sb1[n][lane];
            float d0 = c.x, d1 = c.y, d2 = c.x, d3 = c.y;
            #pragma unroll
            for (int s = 0; s < 4; s++) {
                const uint2 b = sB1h[n][s][lane];
                mma_bf16(d0, d1, d2, d3, hiA[s][0], hiA[s][1], hiA[s][2], hiA[s][3], b.x, b.y);
            }
            #pragma unroll
            for (int s = 0; s < 4; s++) {
                const uint2 b = sB1l[n][s][lane];
                mma_bf16(d0, d1, d2, d3, hiA[s][0], hiA[s][1], hiA[s][2], hiA[s][3], b.x, b.y);
            }
            #pragma unroll
            for (int s = 0; s < 4; s++) {
                const uint2 b = sB1h[n][s][lane];
                mma_bf16(d0, d1, d2, d3, loA[s][0], loA[s][1], loA[s][2], loA[s][3], b.x, b.y);
            }
            D1[n][0] = fmaxf(d0, 0.0f);
            D1[n][1] = fmaxf(d1, 0.0f);
            D1[n][2] = fmaxf(d2, 0.0f);
            D1[n][3] = fmaxf(d3, 0.0f);
        }

        // ---- h fragments: GEMM1 D layout == GEMM2 A layout ----
        u32 hiH[2][4], loH[2][4];
        #pragma unroll
        for (int k = 0; k < 2; k++) {
            split2(D1[2 * k][0],     D1[2 * k][1],     hiH[k][0], loH[k][0]); // a0: row g,  cols 2t..
            split2(D1[2 * k][2],     D1[2 * k][3],     hiH[k][1], loH[k][1]); // a1: row g+8
            split2(D1[2 * k + 1][0], D1[2 * k + 1][1], hiH[k][2], loH[k][2]); // a2: cols +8
            split2(D1[2 * k + 1][2], D1[2 * k + 1][3], hiH[k][3], loH[k][3]); // a3
        }

        // ---- GEMM2 + store ----
        float* yb = y + (size_t)tile * (16 * 16);
        #pragma unroll
        for (int n = 0; n < 2; n++) {
            const float2 c = sb2[n][lane];
            float d0 = c.x, d1 = c.y, d2 = c.x, d3 = c.y;
            #pragma unroll
            for (int k = 0; k < 2; k++) {
                const uint2 b = sB2h[n][k][lane];
                mma_bf16(d0, d1, d2, d3, hiH[k][0], hiH[k][1], hiH[k][2], hiH[k][3], b.x, b.y);
            }
            #pragma unroll
            for (int k = 0; k < 2; k++) {
                const uint2 b = sB2l[n][k][lane];
                mma_bf16(d0, d1, d2, d3, hiH[k][0], hiH[k][1], hiH[k][2], hiH[k][3], b.x, b.y);
            }
            #pragma unroll
            for (int k = 0; k < 2; k++) {
                const uint2 b = sB2h[n][k][lane];
                mma_bf16(d0, d1, d2, d3, loH[k][0], loH[k][1], loH[k][2], loH[k][3], b.x, b.y);
            }
            *(float2*)(yb + (size_t)g * 16 + 8 * n + 2 * t)       = make_float2(d0, d1);
            *(float2*)(yb + (size_t)(g + 8) * 16 + 8 * n + 2 * t) = make_float2(d2, d3);
        }
    }
}

extern "C" void kernel_launch(void* const* d_in, const int* in_sizes, int n_in,
                              void* d_out, int out_size) {
    const float* x  = (const float*)d_in[0];
    const float* W1 = (const float*)d_in[1];
    const float* b1 = (const float*)d_in[2];
    const float* W2 = (const float*)d_in[3];
    const float* b2 = (const float*)d_in[4];
    float* y = (float*)d_out;

    const int B = in_sizes[0] / 64;
    const int nTiles = B / 16;              // 65536

    // 64-thread CTAs: ~130 regs -> ~7 CTAs/SM (14 warps), smem 12KB/CTA.
    const int blocks = 1064;                // 152 SMs * 7
    livenet_mma<<<blocks, 64>>>(x, W1, b1, W2, b2, y, nTiles);
}

// round 6
// speedup vs baseline: 2.3846x; 1.3108x over previous
#include <cuda_runtime.h>
#include <cuda_bf16.h>
#include <cstdint>

// LiveNet: y = relu(x @ W1 + b1) @ W2 + b2
// B=1048576, N_IN=64, N_MID=32, N_OUT=16, fp32.
//
// R6: R5 (warp-level mma.sync bf16x3 split) + software-pipelined register
// prefetch of the next x tile. R5 was latency-bound (occ 10.8%, issue 19.6%,
// no pipe >50%): each iteration serialized LDG -> split -> MMA. Now the next
// tile's 16 LDG.64 issue as soon as the current xv registers are consumed,
// hiding DRAM latency behind ~60 MMAs + epilogue.

typedef uint32_t u32;

__device__ __forceinline__ u32 cvt_bf16x2(float hi, float lo) {
    u32 r; asm("cvt.rn.bf16x2.f32 %0, %1, %2;" : "=r"(r) : "f"(hi), "f"(lo)); return r;
}
// split pair (x0=k even -> low bf16, x1=k odd -> high bf16)
__device__ __forceinline__ void split2(float x0, float x1, u32& hi, u32& lo) {
    hi = cvt_bf16x2(x1, x0);
    const float e0 = __uint_as_float(__byte_perm(hi, 0, 0x1044));
    const float e1 = __uint_as_float(__byte_perm(hi, 0, 0x3244));
    lo = cvt_bf16x2(x1 - e1, x0 - e0);
}
__device__ __forceinline__ void mma_bf16(float& d0, float& d1, float& d2, float& d3,
                                         u32 a0, u32 a1, u32 a2, u32 a3,
                                         u32 b0, u32 b1) {
    asm("mma.sync.aligned.m16n8k16.row.col.f32.bf16.bf16.f32 "
        "{%0,%1,%2,%3}, {%4,%5,%6,%7}, {%8,%9}, {%0,%1,%2,%3};"
        : "+f"(d0), "+f"(d1), "+f"(d2), "+f"(d3)
        : "r"(a0), "r"(a1), "r"(a2), "r"(a3), "r"(b0), "r"(b1));
}

__global__ __launch_bounds__(128)
void livenet_mma(const float* __restrict__ x,
                 const float* __restrict__ W1,
                 const float* __restrict__ b1,
                 const float* __restrict__ W2,
                 const float* __restrict__ b2,
                 float* __restrict__ y,
                 int nTiles) {
    __shared__ uint2  sB1h[4][4][32];   // [ntile][kstep][lane] GEMM1 W hi
    __shared__ uint2  sB1l[4][4][32];
    __shared__ uint2  sB2h[2][2][32];   // [ntile][kstep][lane] GEMM2 W hi
    __shared__ uint2  sB2l[2][2][32];
    __shared__ float2 sb1[4][32];       // bias fragments (C operand pairs)
    __shared__ float2 sb2[2][32];

    const int tid  = threadIdx.x;
    const int wid  = tid >> 5;
    const int lane = tid & 31;
    const int g = lane >> 2;     // fragment group row
    const int t = lane & 3;      // thread-in-group

    // ---- one-time fragment build (warp 0) ----
    if (wid == 0) {
        #pragma unroll
        for (int n = 0; n < 4; n++) {
            #pragma unroll
            for (int s = 0; s < 4; s++) {
                const int col = 8 * n + g;
                const float w00 = W1[(16 * s + 2 * t)     * 32 + col];
                const float w01 = W1[(16 * s + 2 * t + 1) * 32 + col];
                const float w10 = W1[(16 * s + 2 * t + 8) * 32 + col];
                const float w11 = W1[(16 * s + 2 * t + 9) * 32 + col];
                u32 h0, l0, h1, l1;
                split2(w00, w01, h0, l0);
                split2(w10, w11, h1, l1);
                sB1h[n][s][lane] = make_uint2(h0, h1);
                sB1l[n][s][lane] = make_uint2(l0, l1);
            }
            sb1[n][lane] = make_float2(b1[8 * n + 2 * t], b1[8 * n + 2 * t + 1]);
        }
        #pragma unroll
        for (int n = 0; n < 2; n++) {
            #pragma unroll
            for (int k = 0; k < 2; k++) {
                const int col = 8 * n + g;
                const float w00 = W2[(16 * k + 2 * t)     * 16 + col];
                const float w01 = W2[(16 * k + 2 * t + 1) * 16 + col];
                const float w10 = W2[(16 * k + 2 * t + 8) * 16 + col];
                const float w11 = W2[(16 * k + 2 * t + 9) * 16 + col];
                u32 h0, l0, h1, l1;
                split2(w00, w01, h0, l0);
                split2(w10, w11, h1, l1);
                sB2h[n][k][lane] = make_uint2(h0, h1);
                sB2l[n][k][lane] = make_uint2(l0, l1);
            }
            sb2[n][lane] = make_float2(b2[8 * n + 2 * t], b2[8 * n + 2 * t + 1]);
        }
    }
    __syncthreads();

    const int nWarps = gridDim.x * 4;
    const int gw     = blockIdx.x * 4 + wid;

    // lane-fixed byte offset within a tile for the 16 x-loads
    const size_t lbase = (size_t)g * 64 + 2 * t;

    int tile = gw;
    if (tile >= nTiles) return;

    // ---- prologue: load first tile ----
    float2 xv[2][8];
    {
        const float* xb = x + (size_t)tile * 1024 + lbase;
        #pragma unroll
        for (int rh = 0; rh < 2; rh++)
            #pragma unroll
            for (int u = 0; u < 8; u++)
                xv[rh][u] = *(const float2*)(xb + 512 * rh + 8 * u);
    }

    while (true) {
        // ---- consume xv into A fragments (hi/lo split) ----
        u32 hiA[4][4], loA[4][4];
        #pragma unroll
        for (int s = 0; s < 4; s++) {
            split2(xv[0][2 * s].x,     xv[0][2 * s].y,     hiA[s][0], loA[s][0]);
            split2(xv[1][2 * s].x,     xv[1][2 * s].y,     hiA[s][1], loA[s][1]);
            split2(xv[0][2 * s + 1].x, xv[0][2 * s + 1].y, hiA[s][2], loA[s][2]);
            split2(xv[1][2 * s + 1].x, xv[1][2 * s + 1].y, hiA[s][3], loA[s][3]);
        }

        // ---- prefetch next tile (xv regs now free) ----
        const int ntile = tile + nWarps;
        if (ntile < nTiles) {
            const float* xb = x + (size_t)ntile * 1024 + lbase;
            #pragma unroll
            for (int rh = 0; rh < 2; rh++)
                #pragma unroll
                for (int u = 0; u < 8; u++)
                    xv[rh][u] = *(const float2*)(xb + 512 * rh + 8 * u);
        }

        // ---- GEMM1: D1[n] = x @ W1[:,8n:8n+8] + b1, 3-term split ----
        float D1[4][4];
        #pragma unroll
        for (int n = 0; n < 4; n++) {
            const float2 c = sb1[n][lane];
            float d0 = c.x, d1 = c.y, d2 = c.x, d3 = c.y;
            #pragma unroll
            for (int s = 0; s < 4; s++) {
                const uint2 b = sB1h[n][s][lane];
                mma_bf16(d0, d1, d2, d3, hiA[s][0], hiA[s][1], hiA[s][2], hiA[s][3], b.x, b.y);
            }
            #pragma unroll
            for (int s = 0; s < 4; s++) {
                const uint2 b = sB1l[n][s][lane];
                mma_bf16(d0, d1, d2, d3, hiA[s][0], hiA[s][1], hiA[s][2], hiA[s][3], b.x, b.y);
            }
            #pragma unroll
            for (int s = 0; s < 4; s++) {
                const uint2 b = sB1h[n][s][lane];
                mma_bf16(d0, d1, d2, d3, loA[s][0], loA[s][1], loA[s][2], loA[s][3], b.x, b.y);
            }
            D1[n][0] = fmaxf(d0, 0.0f);
            D1[n][1] = fmaxf(d1, 0.0f);
            D1[n][2] = fmaxf(d2, 0.0f);
            D1[n][3] = fmaxf(d3, 0.0f);
        }

        // ---- h fragments: GEMM1 D layout == GEMM2 A layout ----
        u32 hiH[2][4], loH[2][4];
        #pragma unroll
        for (int k = 0; k < 2; k++) {
            split2(D1[2 * k][0],     D1[2 * k][1],     hiH[k][0], loH[k][0]);
            split2(D1[2 * k][2],     D1[2 * k][3],     hiH[k][1], loH[k][1]);
            split2(D1[2 * k + 1][0], D1[2 * k + 1][1], hiH[k][2], loH[k][2]);
            split2(D1[2 * k + 1][2], D1[2 * k + 1][3], hiH[k][3], loH[k][3]);
        }

        // ---- GEMM2 + store ----
        float* yb = y + (size_t)tile * 256;
        #pragma unroll
        for (int n = 0; n < 2; n++) {
            const float2 c = sb2[n][lane];
            float d0 = c.x, d1 = c.y, d2 = c.x, d3 = c.y;
            #pragma unroll
            for (int k = 0; k < 2; k++) {
                const uint2 b = sB2h[n][k][lane];
                mma_bf16(d0, d1, d2, d3, hiH[k][0], hiH[k][1], hiH[k][2], hiH[k][3], b.x, b.y);
            }
            #pragma unroll
            for (int k = 0; k < 2; k++) {
                const uint2 b = sB2l[n][k][lane];
                mma_bf16(d0, d1, d2, d3, hiH[k][0], hiH[k][1], hiH[k][2], hiH[k][3], b.x, b.y);
            }
            #pragma unroll
            for (int k = 0; k < 2; k++) {
                const uint2 b = sB2h[n][k][lane];
                mma_bf16(d0, d1, d2, d3, loH[k][0], loH[k][1], loH[k][2], loH[k][3], b.x, b.y);
            }
            *(float2*)(yb + (size_t)g * 16 + 8 * n + 2 * t)       = make_float2(d0, d1);
            *(float2*)(yb + (size_t)(g + 8) * 16 + 8 * n + 2 * t) = make_float2(d2, d3);
        }

        if (ntile >= nTiles) break;
        tile = ntile;
    }
}

extern "C" void kernel_launch(void* const* d_in, const int* in_sizes, int n_in,
                              void* d_out, int out_size) {
    const float* x  = (const float*)d_in[0];
    const float* W1 = (const float*)d_in[1];
    const float* b1 = (const float*)d_in[2];
    const float* W2 = (const float*)d_in[3];
    const float* b2 = (const float*)d_in[4];
    float* y = (float*)d_out;

    const int B = in_sizes[0] / 64;
    const int nTiles = B / 16;              // 65536

    // 128-thread blocks; ~200 regs -> ~2 blocks/SM (8 warps), each warp
    // iterates ~54 tiles with prefetch-hidden DRAM latency.
    const int blocks = 304;                 // 152 SMs * 2
    livenet_mma<<<blocks, 128>>>(x, W1, b1, W2, b2, y, nTiles);
}